// round 6
// baseline (speedup 1.0000x reference)
#include <cuda_runtime.h>

// BilinearSampler: B=16, H=256, W=256, C=32, fp32, NHWC.
//
// R4: the flat kernel is at the L2 (LTS) bandwidth wall: 4x128B random corner
// gathers per pixel = ~12.7 TB/s through L2. Restructure for locality:
//   1. bin every sample by its source 16x16 input tile (4096 bins),
//   2. counting sort (hist -> scan -> scatter) into sorted (sid, x, y),
//   3. one CTA per bin: load the 17x17-pixel apron region (37KB) to SMEM once,
//      serve all of the bin's samples from SMEM, write out with streaming stores.
// L2 gather traffic collapses from ~540MB to ~150MB of coalesced region loads.

#define BS_B 16
#define BS_H 256
#define BS_W 256
#define BS_C 32
#define TILE 16
#define TPB_X (BS_W / TILE)            // 16
#define BINS_PER_B (TPB_X * TPB_X)     // 256
#define NBINS (BS_B * BINS_PER_B)      // 4096
#define NSAMP (BS_B * BS_H * BS_W)     // 1048576
#define RDIM  (TILE + 1)               // 17 (region rows/cols incl. apron)

__device__ unsigned g_hist[NBINS];
__device__ unsigned g_base[NBINS];
__device__ unsigned g_cur[NBINS];
__device__ unsigned g_sid[NSAMP];
__device__ float    g_sx[NSAMP];
__device__ float    g_sy[NSAMP];

__device__ __forceinline__ unsigned sample_bin(unsigned pix, float xsv, float ysv) {
    const float x = 0.5f * (xsv + 1.0f) * (float)(BS_W - 1);
    const float y = 0.5f * (ysv + 1.0f) * (float)(BS_H - 1);
    int x0 = __float2int_rd(x);
    int y0 = __float2int_rd(y);
    int x0c = min(max(x0, 0), BS_W - 1);
    int y0c = min(max(y0, 0), BS_H - 1);
    unsigned b = pix >> 16;  // H*W = 65536
    return b * BINS_PER_B + (unsigned)(y0c >> 4) * TPB_X + (unsigned)(x0c >> 4);
}

__global__ void zero_hist_kernel() {
    unsigned i = blockIdx.x * blockDim.x + threadIdx.x;
    if (i < NBINS) g_hist[i] = 0u;
}

__global__ __launch_bounds__(256) void hist_kernel(const float* __restrict__ xs,
                                                   const float* __restrict__ ys) {
    unsigned pix = blockIdx.x * blockDim.x + threadIdx.x;
    if (pix >= NSAMP) return;
    unsigned bin = sample_bin(pix, __ldg(&xs[pix]), __ldg(&ys[pix]));
    atomicAdd(&g_hist[bin], 1u);
}

// Single block, 1024 threads, 4 bins each: exclusive scan of g_hist -> g_base/g_cur.
__global__ __launch_bounds__(1024) void scan_kernel() {
    __shared__ unsigned wsum[32];
    const unsigned tid = threadIdx.x;
    const unsigned lane = tid & 31u, wid = tid >> 5;

    const unsigned i0 = tid * 4;
    unsigned v0 = g_hist[i0], v1 = g_hist[i0 + 1], v2 = g_hist[i0 + 2], v3 = g_hist[i0 + 3];
    const unsigned tot = v0 + v1 + v2 + v3;

    unsigned x = tot;
#pragma unroll
    for (int off = 1; off < 32; off <<= 1) {
        unsigned y = __shfl_up_sync(0xffffffffu, x, off);
        if (lane >= (unsigned)off) x += y;
    }
    if (lane == 31) wsum[wid] = x;
    __syncthreads();
    if (wid == 0) {
        unsigned w = wsum[lane];
#pragma unroll
        for (int off = 1; off < 32; off <<= 1) {
            unsigned y = __shfl_up_sync(0xffffffffu, w, off);
            if (lane >= (unsigned)off) w += y;
        }
        wsum[lane] = w;  // inclusive sums of warp totals
    }
    __syncthreads();

    const unsigned warp_excl = (wid == 0) ? 0u : wsum[wid - 1];
    const unsigned thr_excl = warp_excl + (x - tot);
    unsigned e0 = thr_excl, e1 = e0 + v0, e2 = e1 + v1, e3 = e2 + v2;
    g_base[i0] = e0; g_base[i0 + 1] = e1; g_base[i0 + 2] = e2; g_base[i0 + 3] = e3;
    g_cur[i0]  = e0; g_cur[i0 + 1]  = e1; g_cur[i0 + 2]  = e2; g_cur[i0 + 3]  = e3;
}

__global__ __launch_bounds__(256) void scatter_kernel(const float* __restrict__ xs,
                                                      const float* __restrict__ ys) {
    unsigned pix = blockIdx.x * blockDim.x + threadIdx.x;
    if (pix >= NSAMP) return;
    const float xsv = __ldg(&xs[pix]);
    const float ysv = __ldg(&ys[pix]);
    unsigned bin = sample_bin(pix, xsv, ysv);
    unsigned pos = atomicAdd(&g_cur[bin], 1u);
    g_sid[pos] = pix;
    g_sx[pos] = xsv;
    g_sy[pos] = ysv;
}

__global__ __launch_bounds__(256) void sample_kernel(const float* __restrict__ img,
                                                     float* __restrict__ out) {
    __shared__ float tile[RDIM * RDIM * BS_C];  // 17*17*32 floats = 36,992 B

    const unsigned bin = blockIdx.x;
    const unsigned b  = bin >> 8;
    const int gy0 = (int)((bin >> 4) & 15u) * TILE;
    const int gx0 = (int)(bin & 15u) * TILE;
    const unsigned tid = threadIdx.x;

    // Cooperative region load: 17x17 pixels x 8 float4 = 2312 units.
    const unsigned NU = RDIM * RDIM * (BS_C / 4);
    const unsigned img_b = b * 65536u;
    for (unsigned u = tid; u < NU; u += 256u) {
        unsigned p = u >> 3, c4 = u & 7u;
        unsigned ry = p / RDIM;
        unsigned rx = p - ry * RDIM;
        int gy = min(gy0 + (int)ry, BS_H - 1);
        int gx = min(gx0 + (int)rx, BS_W - 1);
        const float4* src =
            (const float4*)&img[((img_b + (unsigned)(gy * BS_W + gx)) * BS_C) + c4 * 4u];
        ((float4*)tile)[u] = __ldg(src);
    }
    __syncthreads();

    const unsigned start = g_base[bin];
    const unsigned cnt   = g_hist[bin];
    const unsigned grp = tid >> 3;   // 32 sample-groups per CTA
    const unsigned c4  = tid & 7u;
    const unsigned co  = c4 * 4u;

    for (unsigned s = start + grp; s < start + cnt; s += 32u) {
        const unsigned sid = g_sid[s];     // 8-lane broadcast
        const float xsv = g_sx[s];
        const float ysv = g_sy[s];

        const float x = 0.5f * (xsv + 1.0f) * (float)(BS_W - 1);
        const float y = 0.5f * (ysv + 1.0f) * (float)(BS_H - 1);
        int x0 = __float2int_rd(x);
        int y0 = __float2int_rd(y);
        int x0c = min(max(x0, 0), BS_W - 1);
        int x1c = min(max(x0 + 1, 0), BS_W - 1);
        int y0c = min(max(y0, 0), BS_H - 1);
        int y1c = min(max(y0 + 1, 0), BS_H - 1);

        const float x0f = (float)x0c, x1f = (float)x1c;
        const float y0f = (float)y0c, y1f = (float)y1c;
        const float wa = (x1f - x) * (y1f - y);
        const float wb = (x1f - x) * (y - y0f);
        const float wc = (x - x0f) * (y1f - y);
        const float wd = (x - x0f) * (y - y0f);

        // Local region coords. x0c is in [gx0, gx0+15] by bin construction;
        // x1c <= gx0+16 and the clamped border column duplicates row/col 255.
        const int lx0 = x0c - gx0;
        const int lx1 = x1c - gx0;
        const int ly0 = y0c - gy0;
        const int ly1 = y1c - gy0;

        const float4 Ia = *(const float4*)&tile[((unsigned)(ly0 * RDIM + lx0) * BS_C) + co];
        const float4 Ib = *(const float4*)&tile[((unsigned)(ly1 * RDIM + lx0) * BS_C) + co];
        const float4 Ic = *(const float4*)&tile[((unsigned)(ly0 * RDIM + lx1) * BS_C) + co];
        const float4 Id = *(const float4*)&tile[((unsigned)(ly1 * RDIM + lx1) * BS_C) + co];

        float4 r;
        r.x = wa * Ia.x + wb * Ib.x + wc * Ic.x + wd * Id.x;
        r.y = wa * Ia.y + wb * Ib.y + wc * Ic.y + wd * Id.y;
        r.z = wa * Ia.z + wb * Ib.z + wc * Ic.z + wd * Id.z;
        r.w = wa * Ia.w + wb * Ib.w + wc * Ic.w + wd * Id.w;

        __stcs((float4*)&out[sid * (unsigned)BS_C + co], r);
    }
}

extern "C" void kernel_launch(void* const* d_in, const int* in_sizes, int n_in,
                              void* d_out, int out_size) {
    const float* img = (const float*)d_in[0];
    const float* xs  = (const float*)d_in[1];
    const float* ys  = (const float*)d_in[2];
    float* out = (float*)d_out;

    zero_hist_kernel<<<(NBINS + 255) / 256, 256>>>();
    hist_kernel<<<NSAMP / 256, 256>>>(xs, ys);
    scan_kernel<<<1, 1024>>>();
    scatter_kernel<<<NSAMP / 256, 256>>>(xs, ys);
    sample_kernel<<<NBINS, 256>>>(img, out);
}

// round 7
// speedup vs baseline: 2.5634x; 2.5634x over previous
#include <cuda_runtime.h>

// BilinearSampler: B=16, H=256, W=256, C=32, fp32, NHWC.
//
// R6: back to the flat kernel (binning aux passes cost >> savings).
// R3's 4-px/thread batching was silently defeated by ptxas sinking the
// loads (regs stayed 32). This version forces the schedule with compiler
// memory fences: phase 1 computes all 16 corner addresses, phase 2 issues
// all 16 gathers, phase 3 consumes. Registers are expected to jump to
// ~90+, occupancy drops, but per-SM loads-in-flight roughly doubles.

#define BS_B 16
#define BS_H 256
#define BS_W 256
#define BS_C 32          // floats per pixel
#define BS_C4 (BS_C / 4) // float4 per pixel = 8
#define PXT 4            // pixels per thread

__global__ __launch_bounds__(256) void bilinear_sampler_kernel(
    const float* __restrict__ img,   // [B,H,W,C]
    const float* __restrict__ xs,    // [B,H,W]
    const float* __restrict__ ys,    // [B,H,W]
    float* __restrict__ out)         // [B,H,W,C]
{
    const unsigned total = (unsigned)BS_B * BS_H * BS_W * BS_C4; // 8,388,608
    const unsigned q     = total / PXT;                          // 2,097,152

    unsigned t = blockIdx.x * blockDim.x + threadIdx.x;
    if (t >= q) return;

    const int co = ((int)t & (BS_C4 - 1)) * 4;

    unsigned pix[PXT];
    float xc[PXT], yc[PXT];

    // ---- phase 0: batch coordinate loads (8 independent loads) ----
#pragma unroll
    for (int i = 0; i < PXT; i++) {
        unsigned e = t + (unsigned)i * q;
        pix[i] = e >> 3;
        xc[i] = __ldg(&xs[pix[i]]);
        yc[i] = __ldg(&ys[pix[i]]);
    }

    // ---- phase 1: all addresses + weights ----
    const float4* pa[PXT]; const float4* pb[PXT];
    const float4* pc[PXT]; const float4* pd[PXT];
    float wa[PXT], wb[PXT], wc[PXT], wd[PXT];

#pragma unroll
    for (int i = 0; i < PXT; i++) {
        const float x = 0.5f * (xc[i] + 1.0f) * (float)(BS_W - 1);
        const float y = 0.5f * (yc[i] + 1.0f) * (float)(BS_H - 1);

        int x0 = __float2int_rd(x);
        int y0 = __float2int_rd(y);

        int x0c = min(max(x0, 0), BS_W - 1);
        int x1c = min(max(x0 + 1, 0), BS_W - 1);
        int y0c = min(max(y0, 0), BS_H - 1);
        int y1c = min(max(y0 + 1, 0), BS_H - 1);

        const float x0f = (float)x0c, x1f = (float)x1c;
        const float y0f = (float)y0c, y1f = (float)y1c;
        wa[i] = (x1f - x) * (y1f - y);
        wb[i] = (x1f - x) * (y - y0f);
        wc[i] = (x - x0f) * (y1f - y);
        wd[i] = (x - x0f) * (y - y0f);

        const unsigned bimg = (pix[i] >> 16) * (unsigned)(BS_H * BS_W * BS_C);
        pa[i] = (const float4*)&img[bimg + (unsigned)(y0c * BS_W + x0c) * BS_C + co];
        pb[i] = (const float4*)&img[bimg + (unsigned)(y1c * BS_W + x0c) * BS_C + co];
        pc[i] = (const float4*)&img[bimg + (unsigned)(y0c * BS_W + x1c) * BS_C + co];
        pd[i] = (const float4*)&img[bimg + (unsigned)(y1c * BS_W + x1c) * BS_C + co];
    }

    // Fence: no load may be hoisted above address computation is natural;
    // the important part is the fence BELOW, which stops ptxas/nvcc from
    // sinking individual loads down to their first use.
    asm volatile("" ::: "memory");

    // ---- phase 2: issue all 16 corner gathers back-to-back ----
    float4 Ia[PXT], Ib[PXT], Ic[PXT], Id[PXT];
#pragma unroll
    for (int i = 0; i < PXT; i++) {
        Ia[i] = __ldg(pa[i]);
        Ib[i] = __ldg(pb[i]);
        Ic[i] = __ldg(pc[i]);
        Id[i] = __ldg(pd[i]);
    }

    asm volatile("" ::: "memory");

    // ---- phase 3: blend + streaming stores ----
#pragma unroll
    for (int i = 0; i < PXT; i++) {
        float4 r;
        r.x = wa[i] * Ia[i].x + wb[i] * Ib[i].x + wc[i] * Ic[i].x + wd[i] * Id[i].x;
        r.y = wa[i] * Ia[i].y + wb[i] * Ib[i].y + wc[i] * Ic[i].y + wd[i] * Id[i].y;
        r.z = wa[i] * Ia[i].z + wb[i] * Ib[i].z + wc[i] * Ic[i].z + wd[i] * Id[i].z;
        r.w = wa[i] * Ia[i].w + wb[i] * Ib[i].w + wc[i] * Ic[i].w + wd[i] * Id[i].w;
        __stcs((float4*)&out[pix[i] * (unsigned)BS_C + co], r);
    }
}

extern "C" void kernel_launch(void* const* d_in, const int* in_sizes, int n_in,
                              void* d_out, int out_size) {
    const float* img = (const float*)d_in[0];
    const float* xs  = (const float*)d_in[1];
    const float* ys  = (const float*)d_in[2];
    float* out = (float*)d_out;

    const unsigned total = (unsigned)BS_B * BS_H * BS_W * BS_C4;
    const unsigned q     = total / PXT;
    const int threads = 256;
    const int blocks = (int)((q + threads - 1) / threads);
    bilinear_sampler_kernel<<<blocks, threads>>>(img, xs, ys, out);
}